// round 12
// baseline (speedup 1.0000x reference)
#include <cuda_runtime.h>
#include <cuda_bf16.h>
#include <stdint.h>

// Problem constants (fixed by the dataset)
#define B_   8
#define M_   50000
#define D_   256
#define NH_  8
#define GH_  16
#define OUT_ 256
#define SEL_CAP 2048
#define CAND_CAP 4096
#define SEG_ 3125            // 50000 / 16

#define TILE_ROWS 512
#define TILES_PER_B 98               // ceil(50000/512)

// ---------------- scratch (device globals; no allocations) ----------------
__device__ __align__(16) float g_S[B_ * M_];
__device__ __align__(16) float g_colsum[B_ * D_];
__device__ float g_kth[B_];
__device__ int   g_selCount[B_];
__device__ int   g_selIdx[B_ * SEL_CAP];
__device__ __align__(16) float g_num[B_ * OUT_];
__device__ float g_den[B_ * NH_];
__device__ __align__(16) float g_v[B_ * OUT_];
__device__ unsigned g_hist2[B_ * 2048];
__device__ unsigned g_candCnt[B_];
__device__ float g_cand[B_ * CAND_CAP];

// ---------------- helpers ----------------
__device__ __forceinline__ unsigned keyOf(float x) {
    unsigned u = __float_as_uint(x);
    return (u & 0x80000000u) ? ~u : (u | 0x80000000u);
}
__device__ __forceinline__ float invKey(unsigned k) {
    unsigned u = (k & 0x80000000u) ? (k & 0x7FFFFFFFu) : ~k;
    return __uint_as_float(u);
}

// f32x2 packed FMA (Blackwell sm_103a)
#define FMA2(acc, a, b) asm("fma.rn.f32x2 %0, %1, %2, %0;" : "+l"(acc) : "l"(a), "l"(b))
__device__ __forceinline__ unsigned long long packdup(float x) {
    unsigned long long r;
    unsigned xu = __float_as_uint(x);
    asm("mov.b64 %0, {%1, %1};" : "=l"(r) : "r"(xu));
    return r;
}
__device__ __forceinline__ float f2lo(unsigned long long v) {
    return __uint_as_float((unsigned)(v & 0xFFFFFFFFu));
}
__device__ __forceinline__ float f2hi(unsigned long long v) {
    return __uint_as_float((unsigned)(v >> 32));
}

// ---------------- Z: zero all scratch (single launch) ----------------------
__global__ void z_all() {
    int i = blockIdx.x * 256 + threadIdx.x;   // grid 64 -> 16384 threads
    if (i < B_ * D_)   g_colsum[i] = 0.f;
    if (i < B_ * OUT_) g_num[i] = 0.f;
    if (i < B_ * 2048) g_hist2[i] = 0u;
    if (i < B_ * NH_)  g_den[i] = 0.f;
    if (i < B_) { g_selCount[i] = 0; g_candCnt[i] = 0u; }
}

// ---------------- K1: gate scores S + column sums (r7 known-good) ----------
__global__ __launch_bounds__(256, 3) void k1_gate(
    const float* __restrict__ h,
    const float* __restrict__ gsl1_w, const float* __restrict__ gsl1_b,
    const float* __restrict__ gsl2_w, const float* __restrict__ gsl2_b)
{
    extern __shared__ __align__(16) unsigned char smraw[];
    float4* st4 = (float4*)smraw;                                   // 512*8 float4 = 64KB
    unsigned long long* ws = (unsigned long long*)(smraw + 65536);  // 256 u64 = 2KB
    float* csum1 = (float*)(smraw + 65536 + 2048);                  // 256 f = 1KB

    const int tid  = threadIdx.x;
    const int b    = blockIdx.y;
    const int row0 = blockIdx.x * TILE_ROWS;
    const int hseg = tid & 3;
    const int rg   = tid >> 2;
    const int sw8  = tid & 7;
    const int q    = sw8 << 2;

    csum1[tid] = 0.f;

    const float* hb = h + (size_t)b * M_ * D_;
    const unsigned long long* gw = (const unsigned long long*)gsl1_w;

    unsigned long long acc[8][2];
#pragma unroll
    for (int r = 0; r < 8; r++) { acc[r][0] = 0ULL; acc[r][1] = 0ULL; }

    for (int ch = 0; ch < 8; ++ch) {
        const int c0 = ch * 32;
        __syncthreads();

        ws[tid] = gw[c0 * 8 + tid];

        float4 ca = make_float4(0.f, 0.f, 0.f, 0.f);
#pragma unroll
        for (int j = 0; j < 16; ++j) {
            int f = tid + 256 * j;
            int r = f >> 3;
            int gr = row0 + r;
            float4 v = make_float4(0.f, 0.f, 0.f, 0.f);
            if (gr < M_) v = *(const float4*)(hb + (size_t)gr * D_ + c0 + q);
            ca.x += v.x; ca.y += v.y; ca.z += v.z; ca.w += v.w;
            st4[r * 8 + (sw8 ^ ((r >> 3) & 7))] = v;
        }
        atomicAdd(&csum1[c0 + q + 0], ca.x);
        atomicAdd(&csum1[c0 + q + 1], ca.y);
        atomicAdd(&csum1[c0 + q + 2], ca.z);
        atomicAdd(&csum1[c0 + q + 3], ca.w);
        __syncthreads();

#pragma unroll
        for (int cg = 0; cg < 8; ++cg) {
            ulonglong2 w0 = *(const ulonglong2*)&ws[(cg * 4 + 0) * 8 + hseg * 2];
            ulonglong2 w1 = *(const ulonglong2*)&ws[(cg * 4 + 1) * 8 + hseg * 2];
            ulonglong2 w2 = *(const ulonglong2*)&ws[(cg * 4 + 2) * 8 + hseg * 2];
            ulonglong2 w3 = *(const ulonglong2*)&ws[(cg * 4 + 3) * 8 + hseg * 2];
            const int slot = cg ^ (rg & 7);
#pragma unroll
            for (int rr = 0; rr < 8; ++rr) {
                float4 x4 = st4[(rg * 8 + rr) * 8 + slot];
                unsigned long long xx;
                xx = packdup(x4.x); FMA2(acc[rr][0], xx, w0.x); FMA2(acc[rr][1], xx, w0.y);
                xx = packdup(x4.y); FMA2(acc[rr][0], xx, w1.x); FMA2(acc[rr][1], xx, w1.y);
                xx = packdup(x4.z); FMA2(acc[rr][0], xx, w2.x); FMA2(acc[rr][1], xx, w2.y);
                xx = packdup(x4.w); FMA2(acc[rr][0], xx, w3.x); FMA2(acc[rr][1], xx, w3.y);
            }
        }
    }
    __syncthreads();

    {
        const int u0 = 4 * hseg;
        const float b1a = gsl1_b[u0 + 0], b1b = gsl1_b[u0 + 1];
        const float b1c = gsl1_b[u0 + 2], b1d = gsl1_b[u0 + 3];
        const float w2a = gsl2_w[u0 + 0], w2b = gsl2_w[u0 + 1];
        const float w2c = gsl2_w[u0 + 2], w2d = gsl2_w[u0 + 3];

        float zr[8];
#pragma unroll
        for (int rr = 0; rr < 8; ++rr) {
            float z = 0.f;
            z = fmaf(fmaxf(f2lo(acc[rr][0]) + b1a, 0.f), w2a, z);
            z = fmaf(fmaxf(f2hi(acc[rr][0]) + b1b, 0.f), w2b, z);
            z = fmaf(fmaxf(f2lo(acc[rr][1]) + b1c, 0.f), w2c, z);
            z = fmaf(fmaxf(f2hi(acc[rr][1]) + b1d, 0.f), w2d, z);
            z += __shfl_xor_sync(0xFFFFFFFFu, z, 1);
            z += __shfl_xor_sync(0xFFFFFFFFu, z, 2);
            zr[rr] = z;
        }
        if (hseg == 0) {
            const float b2 = gsl2_b[0];
            const int base = row0 + rg * 8;
            if (base + 8 <= M_) {
                float4 s0, s1;
                s0.x = 1.0f / (1.0f + expf(-(zr[0] + b2)));
                s0.y = 1.0f / (1.0f + expf(-(zr[1] + b2)));
                s0.z = 1.0f / (1.0f + expf(-(zr[2] + b2)));
                s0.w = 1.0f / (1.0f + expf(-(zr[3] + b2)));
                s1.x = 1.0f / (1.0f + expf(-(zr[4] + b2)));
                s1.y = 1.0f / (1.0f + expf(-(zr[5] + b2)));
                s1.z = 1.0f / (1.0f + expf(-(zr[6] + b2)));
                s1.w = 1.0f / (1.0f + expf(-(zr[7] + b2)));
                *(float4*)&g_S[(size_t)b * M_ + base] = s0;
                *(float4*)&g_S[(size_t)b * M_ + base + 4] = s1;
            }
        }
    }

    atomicAdd(&g_colsum[b * D_ + tid], csum1[tid]);
}

// ---------------- K2a: parallel top-11-bit histogram of S ------------------
__global__ __launch_bounds__(256) void k2a() {
    const int b = blockIdx.y, seg = blockIdx.x;   // (16, B_)
    const int tid = threadIdx.x;
    __shared__ unsigned hist[2048];
    for (int i = tid; i < 2048; i += 256) hist[i] = 0u;
    __syncthreads();
    const float* Sb = &g_S[(size_t)b * M_];
    const int lo = seg * SEG_, hi = lo + SEG_;
    for (int i = lo + tid; i < hi; i += 256)
        atomicAdd(&hist[keyOf(Sb[i]) >> 21], 1u);
    __syncthreads();
    for (int i = tid; i < 2048; i += 256)
        if (hist[i]) atomicAdd(&g_hist2[b * 2048 + i], hist[i]);
}

// ---------------- parallel bin pick (block-wide, from shared hist) ---------
// 32 warps each reduce a group of NBINS/32 bins; thread 0 then walks only
// 32 group sums + NBINS/32 in-group bins serially from shared.
// Result in sOut[0]=bin, sOut[1]=remaining need within bin.
template<int NBINS>
__device__ __forceinline__ void pick_bin(const unsigned* hist, unsigned need_in,
                                         unsigned* sGsum, unsigned* sOut)
{
    const int tid = threadIdx.x;
    const int w = tid >> 5, l = tid & 31;
    constexpr int GS = NBINS / 32;
    unsigned s = 0;
#pragma unroll
    for (int i = l; i < GS; i += 32) s += hist[w * GS + i];
#pragma unroll
    for (int m = 16; m; m >>= 1) s += __shfl_xor_sync(0xFFFFFFFFu, s, m);
    if (l == 0) sGsum[w] = s;
    __syncthreads();
    if (tid == 0) {
        unsigned need = need_in, cum = 0;
        int g = 0;
        for (int v = 31; v >= 0; --v) {
            unsigned c = sGsum[v];
            if (cum + c >= need) { g = v; need -= cum; break; }
            cum += c;
        }
        cum = 0;
        int bin = g * GS;
        for (int v = GS - 1; v >= 0; --v) {
            unsigned c = hist[g * GS + v];
            if (cum + c >= need) { bin = g * GS + v; need -= cum; break; }
            cum += c;
        }
        sOut[0] = (unsigned)bin; sOut[1] = need;
    }
    __syncthreads();
}

// ---------------- K2b: refine to exact k-th (1 block / batch) -------------
__global__ __launch_bounds__(1024) void k2b(const int* __restrict__ kptr) {
    const int b = blockIdx.x;
    const int tid = threadIdx.x;
    __shared__ unsigned hist[2048];
    __shared__ unsigned sGsum[32];
    __shared__ unsigned sOut[2];

    int kk = kptr ? *kptr : 500;
    if (kk <= 0 || kk > M_) {
        float kf = __int_as_float(kk);
        if (kf >= 1.f && kf <= (float)M_) kk = (int)kf;
        else kk = kk < 1 ? 1 : M_;
    }
    if (kk > M_) kk = M_;

    // level A: stage global histogram to shared, parallel pick
    for (int i = tid; i < 2048; i += 1024) hist[i] = g_hist2[b * 2048 + i];
    __syncthreads();
    pick_bin<2048>(hist, (unsigned)kk, sGsum, sOut);
    const unsigned binA = sOut[0];
    unsigned needB = sOut[1];
    __syncthreads();

    for (int i = tid; i < 2048; i += 1024) hist[i] = 0u;
    __syncthreads();

    // level B: one full scan — histogram bits [10,21) of bin-A matches,
    // compact survivor values into g_cand
    const float* Sb = &g_S[(size_t)b * M_];
    for (int i = tid; i < M_; i += 1024) {
        float s = Sb[i];
        unsigned key = keyOf(s);
        if ((key >> 21) == binA) {
            atomicAdd(&hist[(key >> 10) & 0x7FFu], 1u);
            unsigned p = atomicAdd(&g_candCnt[b], 1u);
            if (p < CAND_CAP) g_cand[b * CAND_CAP + p] = s;
        }
    }
    __syncthreads();
    pick_bin<2048>(hist, needB, sGsum, sOut);
    const unsigned prefAB = (binA << 21) | (sOut[0] << 10);
    const unsigned needC = sOut[1];
    __syncthreads();

    for (int i = tid; i < 1024; i += 1024) hist[i] = 0u;
    __syncthreads();

    // level C: last 10 bits from candidates (or full-scan fallback)
    const unsigned cnt = atomicAdd(&g_candCnt[b], 0u);
    if (cnt <= CAND_CAP) {
        for (unsigned i = tid; i < cnt; i += 1024) {
            unsigned key = keyOf(g_cand[b * CAND_CAP + i]);
            if ((key >> 10) == (prefAB >> 10)) atomicAdd(&hist[key & 0x3FFu], 1u);
        }
    } else {
        for (int i = tid; i < M_; i += 1024) {
            unsigned key = keyOf(Sb[i]);
            if ((key >> 10) == (prefAB >> 10)) atomicAdd(&hist[key & 0x3FFu], 1u);
        }
    }
    __syncthreads();
    pick_bin<1024>(hist, needC, sGsum, sOut);
    if (tid == 0) g_kth[b] = invKey(prefAB | sOut[0]);
}

// ---------------- K2c: parallel mask + gather ------------------------------
__global__ __launch_bounds__(256) void k2c(float* __restrict__ outmask) {
    const int b = blockIdx.y, seg = blockIdx.x;   // (16, B_)
    const float kth = g_kth[b];
    const int lo = seg * SEG_, hi = lo + SEG_;
    for (int i = lo + threadIdx.x; i < hi; i += 256) {
        float s = g_S[(size_t)b * M_ + i];
        bool sel = s >= kth;
        outmask[b * M_ + i] = sel ? 1.f : 0.f;
        if (sel) {
            int pos = atomicAdd(&g_selCount[b], 1);
            if (pos < SEL_CAP) g_selIdx[b * SEL_CAP + pos] = i;
        }
    }
}

// ---------------- K4: selected-row correction (num / den) -----------------
#define RS 16
__global__ __launch_bounds__(256) void k4_selected(
    const float* __restrict__ h,
    const float* __restrict__ att_w, const float* __restrict__ att_b,
    const float* __restrict__ w_w)
{
    __shared__ __align__(16) float hsh[RS][D_];
    __shared__ float efac[RS][NH_];
    __shared__ float aw[D_ * NH_];

    const int b = blockIdx.y;
    const int tid = threadIdx.x;
    for (int i = tid; i < D_ * NH_; i += 256) aw[i] = att_w[i];

    int cnt = g_selCount[b];
    if (cnt > SEL_CAP) cnt = SEL_CAP;
    const int ngroups = (cnt + RS - 1) / RS;
    const float* hb = h + (size_t)b * M_ * D_;

    for (int g = blockIdx.x; g < ngroups; g += gridDim.x) {
        __syncthreads();
        for (int i = tid; i < RS * (D_ / 4); i += 256) {
            int r = i >> 6, c4 = (i & 63) << 2;
            int si = g * RS + r;
            float4 v = make_float4(0.f, 0.f, 0.f, 0.f);
            if (si < cnt)
                v = *(const float4*)(hb + (size_t)g_selIdx[b * SEL_CAP + si] * D_ + c4);
            *(float4*)&hsh[r][c4] = v;
        }
        __syncthreads();
        if (tid < RS * NH_) {
            int r = tid >> 3, hd = tid & 7;
            float s = 0.f;
            for (int c = 0; c < D_; c++) s = fmaf(hsh[r][c], aw[c * NH_ + hd], s);
            float a = fmaxf(s + att_b[hd], 0.f);
            efac[r][hd] = (g * RS + r < cnt) ? (expf(a) - 1.f) : 0.f;
        }
        __syncthreads();

        const int e = tid;
        float acc[RS];
#pragma unroll
        for (int r = 0; r < RS; r++) acc[r] = 0.f;
        for (int c4 = 0; c4 < D_; c4 += 4) {
            float w0 = __ldg(&w_w[(c4 + 0) * OUT_ + e]);
            float w1 = __ldg(&w_w[(c4 + 1) * OUT_ + e]);
            float w2 = __ldg(&w_w[(c4 + 2) * OUT_ + e]);
            float w3 = __ldg(&w_w[(c4 + 3) * OUT_ + e]);
#pragma unroll
            for (int r = 0; r < RS; r++) {
                float4 hv = *(const float4*)&hsh[r][c4];
                float a = acc[r];
                a = fmaf(hv.x, w0, a);
                a = fmaf(hv.y, w1, a);
                a = fmaf(hv.z, w2, a);
                a = fmaf(hv.w, w3, a);
                acc[r] = a;
            }
        }
        const int hd = e >> 5;
        float s = 0.f;
#pragma unroll
        for (int r = 0; r < RS; r++) s = fmaf(efac[r][hd], acc[r], s);
        atomicAdd(&g_num[b * OUT_ + e], s);
        if (tid < NH_) {
            float d = 0.f;
#pragma unroll
            for (int r = 0; r < RS; r++) d += efac[r][tid];
            atomicAdd(&g_den[b * NH_ + tid], d);
        }
    }
}

// ---------------- K5a: base term + Q_res + combine (col-parallel) ---------
__global__ __launch_bounds__(256) void k5a(
    const float* __restrict__ w_w,
    const float* __restrict__ res_w, const float* __restrict__ res_b)
{
    const int b = blockIdx.y;
    const int e = blockIdx.x * 32 + (threadIdx.x >> 3);
    const int l8 = threadIdx.x & 7;
    __shared__ float cs[D_];
    cs[threadIdx.x] = g_colsum[b * D_ + threadIdx.x];
    __syncthreads();

    float base = 0.f, qr = 0.f;
#pragma unroll 8
    for (int i = 0; i < 32; i++) {
        int c = l8 + 8 * i;
        float x = cs[c];
        base = fmaf(x, __ldg(&w_w[c * OUT_ + e]), base);
        qr   = fmaf(x, __ldg(&res_w[c * OUT_ + e]), qr);
    }
#pragma unroll
    for (int m = 1; m < 8; m <<= 1) {
        base += __shfl_xor_sync(0xFFFFFFFFu, base, m);
        qr   += __shfl_xor_sync(0xFFFFFFFFu, qr, m);
    }
    if (l8 == 0) {
        float Qres = fmaxf(qr * (1.0f / (float)M_) + res_b[e], 0.f);
        float den = (float)M_ + g_den[b * NH_ + (e >> 5)];
        float ov = (base + g_num[b * OUT_ + e]) / den;
        g_v[b * OUT_ + e] = fmaxf(ov + Qres, 0.f);
    }
}

// ---------------- K5b: layernorm of the 256-vector ------------------------
__global__ __launch_bounds__(256) void k5b(float* __restrict__ out)
{
    const int b = blockIdx.x;
    const int e = threadIdx.x;
    __shared__ float red[256];

    float v = g_v[b * OUT_ + e];
    red[e] = v; __syncthreads();
    for (int s = 128; s > 0; s >>= 1) {
        if (e < s) red[e] += red[e + s];
        __syncthreads();
    }
    float mean = red[0] * (1.0f / 256.0f);
    __syncthreads();
    float dm = v - mean;
    red[e] = dm * dm; __syncthreads();
    for (int s = 128; s > 0; s >>= 1) {
        if (e < s) red[e] += red[e + s];
        __syncthreads();
    }
    float var = red[0] * (1.0f / 256.0f);
    out[b * OUT_ + e] = dm * rsqrtf(var + 1e-8f);
}

// ---------------- launch -----------------
#define K1_SMEM (65536 + 2048 + 1024)

extern "C" void kernel_launch(void* const* d_in, const int* in_sizes, int n_in,
                              void* d_out, int out_size)
{
    const float* h      = (const float*)d_in[0];
    const float* att_w  = (const float*)d_in[1];
    const float* att_b  = (const float*)d_in[2];
    const float* w_w    = (const float*)d_in[3];
    const float* res_w  = (const float*)d_in[4];
    const float* res_b  = (const float*)d_in[5];
    const float* gsl1_w = (const float*)d_in[6];
    const float* gsl1_b = (const float*)d_in[7];
    const float* gsl2_w = (const float*)d_in[8];
    const float* gsl2_b = (const float*)d_in[9];
    const int*   kptr   = (n_in > 10) ? (const int*)d_in[10] : nullptr;

    float* out  = (float*)d_out;              // [B, 1, OUT] -> 2048 floats
    float* mask = out + B_ * OUT_;            // [B, 1, M]   -> 400000 floats

    cudaFuncSetAttribute(k1_gate, cudaFuncAttributeMaxDynamicSharedMemorySize, K1_SMEM);

    z_all<<<64, 256>>>();                                   // launch 1
    {
        dim3 grid(TILES_PER_B, B_);                         // launch 2
        k1_gate<<<grid, 256, K1_SMEM>>>(h, gsl1_w, gsl1_b, gsl2_w, gsl2_b);
    }
    {
        dim3 grid(16, B_);                                  // launch 3
        k2a<<<grid, 256>>>();
    }
    k2b<<<B_, 1024>>>(kptr);                                // launch 4 (profiled)
    {
        dim3 grid(16, B_);                                  // launch 5
        k2c<<<grid, 256>>>(mask);
    }
    {
        dim3 grid(64, B_);                                  // launch 6
        k4_selected<<<grid, 256>>>(h, att_w, att_b, w_w);
    }
    {
        dim3 grid(8, B_);                                   // launch 7
        k5a<<<grid, 256>>>(w_w, res_w, res_b);
    }
    k5b<<<B_, 256>>>(out);                                  // launch 8
}

// round 13
// speedup vs baseline: 1.0010x; 1.0010x over previous
#include <cuda_runtime.h>
#include <cuda_bf16.h>
#include <stdint.h>

// Problem constants (fixed by the dataset)
#define B_   8
#define M_   50000
#define D_   256
#define NH_  8
#define GH_  16
#define OUT_ 256
#define SEL_CAP 2048
#define CAND_CAP 4096
#define SEG_ 3125            // 50000 / 16

#define TILE_ROWS 512
#define TILES_PER_B 98               // ceil(50000/512)

// ---------------- scratch (device globals; no allocations) ----------------
__device__ __align__(16) float g_S[B_ * M_];
__device__ __align__(16) float g_colsum[B_ * D_];
__device__ float g_kth[B_];
__device__ int   g_selCount[B_];
__device__ int   g_selIdx[B_ * SEL_CAP];
__device__ __align__(16) float g_num[B_ * OUT_];
__device__ float g_den[B_ * NH_];
__device__ __align__(16) float g_v[B_ * OUT_];
__device__ unsigned g_hist2[B_ * 2048];
__device__ unsigned g_candCnt[B_];
__device__ float g_cand[B_ * CAND_CAP];

// ---------------- helpers ----------------
__device__ __forceinline__ unsigned keyOf(float x) {
    unsigned u = __float_as_uint(x);
    return (u & 0x80000000u) ? ~u : (u | 0x80000000u);
}
__device__ __forceinline__ float invKey(unsigned k) {
    unsigned u = (k & 0x80000000u) ? (k & 0x7FFFFFFFu) : ~k;
    return __uint_as_float(u);
}

// f32x2 packed FMA (Blackwell sm_103a)
#define FMA2(acc, a, b) asm("fma.rn.f32x2 %0, %1, %2, %0;" : "+l"(acc) : "l"(a), "l"(b))
__device__ __forceinline__ unsigned long long packdup(float x) {
    unsigned long long r;
    unsigned xu = __float_as_uint(x);
    asm("mov.b64 %0, {%1, %1};" : "=l"(r) : "r"(xu));
    return r;
}
__device__ __forceinline__ float f2lo(unsigned long long v) {
    return __uint_as_float((unsigned)(v & 0xFFFFFFFFu));
}
__device__ __forceinline__ float f2hi(unsigned long long v) {
    return __uint_as_float((unsigned)(v >> 32));
}

// ---------------- Z: zero all scratch (single launch) ----------------------
__global__ void z_all() {
    int i = blockIdx.x * 256 + threadIdx.x;   // grid 64 -> 16384 threads
    if (i < B_ * D_)   g_colsum[i] = 0.f;
    if (i < B_ * OUT_) g_num[i] = 0.f;
    if (i < B_ * 2048) g_hist2[i] = 0u;
    if (i < B_ * NH_)  g_den[i] = 0.f;
    if (i < B_) { g_selCount[i] = 0; g_candCnt[i] = 0u; }
}

// ---------------- K1: gate scores S + column sums (r7 known-good) ----------
__global__ __launch_bounds__(256, 3) void k1_gate(
    const float* __restrict__ h,
    const float* __restrict__ gsl1_w, const float* __restrict__ gsl1_b,
    const float* __restrict__ gsl2_w, const float* __restrict__ gsl2_b)
{
    extern __shared__ __align__(16) unsigned char smraw[];
    float4* st4 = (float4*)smraw;                                   // 512*8 float4 = 64KB
    unsigned long long* ws = (unsigned long long*)(smraw + 65536);  // 256 u64 = 2KB
    float* csum1 = (float*)(smraw + 65536 + 2048);                  // 256 f = 1KB

    const int tid  = threadIdx.x;
    const int b    = blockIdx.y;
    const int row0 = blockIdx.x * TILE_ROWS;
    const int hseg = tid & 3;
    const int rg   = tid >> 2;
    const int sw8  = tid & 7;
    const int q    = sw8 << 2;

    csum1[tid] = 0.f;

    const float* hb = h + (size_t)b * M_ * D_;
    const unsigned long long* gw = (const unsigned long long*)gsl1_w;

    unsigned long long acc[8][2];
#pragma unroll
    for (int r = 0; r < 8; r++) { acc[r][0] = 0ULL; acc[r][1] = 0ULL; }

    for (int ch = 0; ch < 8; ++ch) {
        const int c0 = ch * 32;
        __syncthreads();

        ws[tid] = gw[c0 * 8 + tid];

        float4 ca = make_float4(0.f, 0.f, 0.f, 0.f);
#pragma unroll
        for (int j = 0; j < 16; ++j) {
            int f = tid + 256 * j;
            int r = f >> 3;
            int gr = row0 + r;
            float4 v = make_float4(0.f, 0.f, 0.f, 0.f);
            if (gr < M_) v = *(const float4*)(hb + (size_t)gr * D_ + c0 + q);
            ca.x += v.x; ca.y += v.y; ca.z += v.z; ca.w += v.w;
            st4[r * 8 + (sw8 ^ ((r >> 3) & 7))] = v;
        }
        atomicAdd(&csum1[c0 + q + 0], ca.x);
        atomicAdd(&csum1[c0 + q + 1], ca.y);
        atomicAdd(&csum1[c0 + q + 2], ca.z);
        atomicAdd(&csum1[c0 + q + 3], ca.w);
        __syncthreads();

#pragma unroll
        for (int cg = 0; cg < 8; ++cg) {
            ulonglong2 w0 = *(const ulonglong2*)&ws[(cg * 4 + 0) * 8 + hseg * 2];
            ulonglong2 w1 = *(const ulonglong2*)&ws[(cg * 4 + 1) * 8 + hseg * 2];
            ulonglong2 w2 = *(const ulonglong2*)&ws[(cg * 4 + 2) * 8 + hseg * 2];
            ulonglong2 w3 = *(const ulonglong2*)&ws[(cg * 4 + 3) * 8 + hseg * 2];
            const int slot = cg ^ (rg & 7);
#pragma unroll
            for (int rr = 0; rr < 8; ++rr) {
                float4 x4 = st4[(rg * 8 + rr) * 8 + slot];
                unsigned long long xx;
                xx = packdup(x4.x); FMA2(acc[rr][0], xx, w0.x); FMA2(acc[rr][1], xx, w0.y);
                xx = packdup(x4.y); FMA2(acc[rr][0], xx, w1.x); FMA2(acc[rr][1], xx, w1.y);
                xx = packdup(x4.z); FMA2(acc[rr][0], xx, w2.x); FMA2(acc[rr][1], xx, w2.y);
                xx = packdup(x4.w); FMA2(acc[rr][0], xx, w3.x); FMA2(acc[rr][1], xx, w3.y);
            }
        }
    }
    __syncthreads();

    {
        const int u0 = 4 * hseg;
        const float b1a = gsl1_b[u0 + 0], b1b = gsl1_b[u0 + 1];
        const float b1c = gsl1_b[u0 + 2], b1d = gsl1_b[u0 + 3];
        const float w2a = gsl2_w[u0 + 0], w2b = gsl2_w[u0 + 1];
        const float w2c = gsl2_w[u0 + 2], w2d = gsl2_w[u0 + 3];

        float zr[8];
#pragma unroll
        for (int rr = 0; rr < 8; ++rr) {
            float z = 0.f;
            z = fmaf(fmaxf(f2lo(acc[rr][0]) + b1a, 0.f), w2a, z);
            z = fmaf(fmaxf(f2hi(acc[rr][0]) + b1b, 0.f), w2b, z);
            z = fmaf(fmaxf(f2lo(acc[rr][1]) + b1c, 0.f), w2c, z);
            z = fmaf(fmaxf(f2hi(acc[rr][1]) + b1d, 0.f), w2d, z);
            z += __shfl_xor_sync(0xFFFFFFFFu, z, 1);
            z += __shfl_xor_sync(0xFFFFFFFFu, z, 2);
            zr[rr] = z;
        }
        if (hseg == 0) {
            const float b2 = gsl2_b[0];
            const int base = row0 + rg * 8;
            if (base + 8 <= M_) {
                float4 s0, s1;
                s0.x = 1.0f / (1.0f + expf(-(zr[0] + b2)));
                s0.y = 1.0f / (1.0f + expf(-(zr[1] + b2)));
                s0.z = 1.0f / (1.0f + expf(-(zr[2] + b2)));
                s0.w = 1.0f / (1.0f + expf(-(zr[3] + b2)));
                s1.x = 1.0f / (1.0f + expf(-(zr[4] + b2)));
                s1.y = 1.0f / (1.0f + expf(-(zr[5] + b2)));
                s1.z = 1.0f / (1.0f + expf(-(zr[6] + b2)));
                s1.w = 1.0f / (1.0f + expf(-(zr[7] + b2)));
                *(float4*)&g_S[(size_t)b * M_ + base] = s0;
                *(float4*)&g_S[(size_t)b * M_ + base + 4] = s1;
            }
        }
    }

    atomicAdd(&g_colsum[b * D_ + tid], csum1[tid]);
}

// ---------------- K2a: parallel top-11-bit histogram of S ------------------
__global__ __launch_bounds__(256) void k2a() {
    const int b = blockIdx.y, seg = blockIdx.x;   // (16, B_)
    const int tid = threadIdx.x;
    __shared__ unsigned hist[2048];
    for (int i = tid; i < 2048; i += 256) hist[i] = 0u;
    __syncthreads();
    const float* Sb = &g_S[(size_t)b * M_];
    const int lo = seg * SEG_, hi = lo + SEG_;
    for (int i = lo + tid; i < hi; i += 256)
        atomicAdd(&hist[keyOf(Sb[i]) >> 21], 1u);
    __syncthreads();
    for (int i = tid; i < 2048; i += 256)
        if (hist[i]) atomicAdd(&g_hist2[b * 2048 + i], hist[i]);
}

// ---------------- parallel bin pick (block-wide, from shared hist) ---------
// 32 warps each reduce a group of NBINS/32 bins; thread 0 then walks only
// 32 group sums + NBINS/32 in-group bins serially from shared.
// Result in sOut[0]=bin, sOut[1]=remaining need within bin.
template<int NBINS>
__device__ __forceinline__ void pick_bin(const unsigned* hist, unsigned need_in,
                                         unsigned* sGsum, unsigned* sOut)
{
    const int tid = threadIdx.x;
    const int w = tid >> 5, l = tid & 31;
    constexpr int GS = NBINS / 32;
    unsigned s = 0;
#pragma unroll
    for (int i = l; i < GS; i += 32) s += hist[w * GS + i];
#pragma unroll
    for (int m = 16; m; m >>= 1) s += __shfl_xor_sync(0xFFFFFFFFu, s, m);
    if (l == 0) sGsum[w] = s;
    __syncthreads();
    if (tid == 0) {
        unsigned need = need_in, cum = 0;
        int g = 0;
        for (int v = 31; v >= 0; --v) {
            unsigned c = sGsum[v];
            if (cum + c >= need) { g = v; need -= cum; break; }
            cum += c;
        }
        cum = 0;
        int bin = g * GS;
        for (int v = GS - 1; v >= 0; --v) {
            unsigned c = hist[g * GS + v];
            if (cum + c >= need) { bin = g * GS + v; need -= cum; break; }
            cum += c;
        }
        sOut[0] = (unsigned)bin; sOut[1] = need;
    }
    __syncthreads();
}

// ---------------- K2b: refine to exact k-th (1 block / batch) -------------
__global__ __launch_bounds__(1024) void k2b(const int* __restrict__ kptr) {
    const int b = blockIdx.x;
    const int tid = threadIdx.x;
    __shared__ unsigned hist[2048];
    __shared__ unsigned sGsum[32];
    __shared__ unsigned sOut[2];

    int kk = kptr ? *kptr : 500;
    if (kk <= 0 || kk > M_) {
        float kf = __int_as_float(kk);
        if (kf >= 1.f && kf <= (float)M_) kk = (int)kf;
        else kk = kk < 1 ? 1 : M_;
    }
    if (kk > M_) kk = M_;

    // level A: stage global histogram to shared, parallel pick
    for (int i = tid; i < 2048; i += 1024) hist[i] = g_hist2[b * 2048 + i];
    __syncthreads();
    pick_bin<2048>(hist, (unsigned)kk, sGsum, sOut);
    const unsigned binA = sOut[0];
    unsigned needB = sOut[1];
    __syncthreads();

    for (int i = tid; i < 2048; i += 1024) hist[i] = 0u;
    __syncthreads();

    // level B: one full scan — histogram bits [10,21) of bin-A matches,
    // compact survivor values into g_cand
    const float* Sb = &g_S[(size_t)b * M_];
    for (int i = tid; i < M_; i += 1024) {
        float s = Sb[i];
        unsigned key = keyOf(s);
        if ((key >> 21) == binA) {
            atomicAdd(&hist[(key >> 10) & 0x7FFu], 1u);
            unsigned p = atomicAdd(&g_candCnt[b], 1u);
            if (p < CAND_CAP) g_cand[b * CAND_CAP + p] = s;
        }
    }
    __syncthreads();
    pick_bin<2048>(hist, needB, sGsum, sOut);
    const unsigned prefAB = (binA << 21) | (sOut[0] << 10);
    const unsigned needC = sOut[1];
    __syncthreads();

    for (int i = tid; i < 1024; i += 1024) hist[i] = 0u;
    __syncthreads();

    // level C: last 10 bits from candidates (or full-scan fallback)
    const unsigned cnt = atomicAdd(&g_candCnt[b], 0u);
    if (cnt <= CAND_CAP) {
        for (unsigned i = tid; i < cnt; i += 1024) {
            unsigned key = keyOf(g_cand[b * CAND_CAP + i]);
            if ((key >> 10) == (prefAB >> 10)) atomicAdd(&hist[key & 0x3FFu], 1u);
        }
    } else {
        for (int i = tid; i < M_; i += 1024) {
            unsigned key = keyOf(Sb[i]);
            if ((key >> 10) == (prefAB >> 10)) atomicAdd(&hist[key & 0x3FFu], 1u);
        }
    }
    __syncthreads();
    pick_bin<1024>(hist, needC, sGsum, sOut);
    if (tid == 0) g_kth[b] = invKey(prefAB | sOut[0]);
}

// ---------------- K2c: parallel mask + gather ------------------------------
__global__ __launch_bounds__(256) void k2c(float* __restrict__ outmask) {
    const int b = blockIdx.y, seg = blockIdx.x;   // (16, B_)
    const float kth = g_kth[b];
    const int lo = seg * SEG_, hi = lo + SEG_;
    for (int i = lo + threadIdx.x; i < hi; i += 256) {
        float s = g_S[(size_t)b * M_ + i];
        bool sel = s >= kth;
        outmask[b * M_ + i] = sel ? 1.f : 0.f;
        if (sel) {
            int pos = atomicAdd(&g_selCount[b], 1);
            if (pos < SEL_CAP) g_selIdx[b * SEL_CAP + pos] = i;
        }
    }
}

// ---------------- K4: selected-row correction (num / den) -----------------
#define RS 16
__global__ __launch_bounds__(256) void k4_selected(
    const float* __restrict__ h,
    const float* __restrict__ att_w, const float* __restrict__ att_b,
    const float* __restrict__ w_w)
{
    __shared__ __align__(16) float hsh[RS][D_];
    __shared__ float efac[RS][NH_];
    __shared__ float aw[D_ * NH_];

    const int b = blockIdx.y;
    const int tid = threadIdx.x;
    for (int i = tid; i < D_ * NH_; i += 256) aw[i] = att_w[i];

    int cnt = g_selCount[b];
    if (cnt > SEL_CAP) cnt = SEL_CAP;
    const int ngroups = (cnt + RS - 1) / RS;
    const float* hb = h + (size_t)b * M_ * D_;

    for (int g = blockIdx.x; g < ngroups; g += gridDim.x) {
        __syncthreads();
        for (int i = tid; i < RS * (D_ / 4); i += 256) {
            int r = i >> 6, c4 = (i & 63) << 2;
            int si = g * RS + r;
            float4 v = make_float4(0.f, 0.f, 0.f, 0.f);
            if (si < cnt)
                v = *(const float4*)(hb + (size_t)g_selIdx[b * SEL_CAP + si] * D_ + c4);
            *(float4*)&hsh[r][c4] = v;
        }
        __syncthreads();
        if (tid < RS * NH_) {
            int r = tid >> 3, hd = tid & 7;
            float s = 0.f;
            for (int c = 0; c < D_; c++) s = fmaf(hsh[r][c], aw[c * NH_ + hd], s);
            float a = fmaxf(s + att_b[hd], 0.f);
            efac[r][hd] = (g * RS + r < cnt) ? (expf(a) - 1.f) : 0.f;
        }
        __syncthreads();

        const int e = tid;
        float acc[RS];
#pragma unroll
        for (int r = 0; r < RS; r++) acc[r] = 0.f;
        for (int c4 = 0; c4 < D_; c4 += 4) {
            float w0 = __ldg(&w_w[(c4 + 0) * OUT_ + e]);
            float w1 = __ldg(&w_w[(c4 + 1) * OUT_ + e]);
            float w2 = __ldg(&w_w[(c4 + 2) * OUT_ + e]);
            float w3 = __ldg(&w_w[(c4 + 3) * OUT_ + e]);
#pragma unroll
            for (int r = 0; r < RS; r++) {
                float4 hv = *(const float4*)&hsh[r][c4];
                float a = acc[r];
                a = fmaf(hv.x, w0, a);
                a = fmaf(hv.y, w1, a);
                a = fmaf(hv.z, w2, a);
                a = fmaf(hv.w, w3, a);
                acc[r] = a;
            }
        }
        const int hd = e >> 5;
        float s = 0.f;
#pragma unroll
        for (int r = 0; r < RS; r++) s = fmaf(efac[r][hd], acc[r], s);
        atomicAdd(&g_num[b * OUT_ + e], s);
        if (tid < NH_) {
            float d = 0.f;
#pragma unroll
            for (int r = 0; r < RS; r++) d += efac[r][tid];
            atomicAdd(&g_den[b * NH_ + tid], d);
        }
    }
}

// ---------------- K5a: base term + Q_res + combine (col-parallel) ---------
__global__ __launch_bounds__(256) void k5a(
    const float* __restrict__ w_w,
    const float* __restrict__ res_w, const float* __restrict__ res_b)
{
    const int b = blockIdx.y;
    const int e = blockIdx.x * 32 + (threadIdx.x >> 3);
    const int l8 = threadIdx.x & 7;
    __shared__ float cs[D_];
    cs[threadIdx.x] = g_colsum[b * D_ + threadIdx.x];
    __syncthreads();

    float base = 0.f, qr = 0.f;
#pragma unroll 8
    for (int i = 0; i < 32; i++) {
        int c = l8 + 8 * i;
        float x = cs[c];
        base = fmaf(x, __ldg(&w_w[c * OUT_ + e]), base);
        qr   = fmaf(x, __ldg(&res_w[c * OUT_ + e]), qr);
    }
#pragma unroll
    for (int m = 1; m < 8; m <<= 1) {
        base += __shfl_xor_sync(0xFFFFFFFFu, base, m);
        qr   += __shfl_xor_sync(0xFFFFFFFFu, qr, m);
    }
    if (l8 == 0) {
        float Qres = fmaxf(qr * (1.0f / (float)M_) + res_b[e], 0.f);
        float den = (float)M_ + g_den[b * NH_ + (e >> 5)];
        float ov = (base + g_num[b * OUT_ + e]) / den;
        g_v[b * OUT_ + e] = fmaxf(ov + Qres, 0.f);
    }
}

// ---------------- K5b: layernorm of the 256-vector ------------------------
__global__ __launch_bounds__(256) void k5b(float* __restrict__ out)
{
    const int b = blockIdx.x;
    const int e = threadIdx.x;
    __shared__ float red[256];

    float v = g_v[b * OUT_ + e];
    red[e] = v; __syncthreads();
    for (int s = 128; s > 0; s >>= 1) {
        if (e < s) red[e] += red[e + s];
        __syncthreads();
    }
    float mean = red[0] * (1.0f / 256.0f);
    __syncthreads();
    float dm = v - mean;
    red[e] = dm * dm; __syncthreads();
    for (int s = 128; s > 0; s >>= 1) {
        if (e < s) red[e] += red[e + s];
        __syncthreads();
    }
    float var = red[0] * (1.0f / 256.0f);
    out[b * OUT_ + e] = dm * rsqrtf(var + 1e-8f);
}

// ---------------- launch -----------------
#define K1_SMEM (65536 + 2048 + 1024)

extern "C" void kernel_launch(void* const* d_in, const int* in_sizes, int n_in,
                              void* d_out, int out_size)
{
    const float* h      = (const float*)d_in[0];
    const float* att_w  = (const float*)d_in[1];
    const float* att_b  = (const float*)d_in[2];
    const float* w_w    = (const float*)d_in[3];
    const float* res_w  = (const float*)d_in[4];
    const float* res_b  = (const float*)d_in[5];
    const float* gsl1_w = (const float*)d_in[6];
    const float* gsl1_b = (const float*)d_in[7];
    const float* gsl2_w = (const float*)d_in[8];
    const float* gsl2_b = (const float*)d_in[9];
    const int*   kptr   = (n_in > 10) ? (const int*)d_in[10] : nullptr;

    float* out  = (float*)d_out;              // [B, 1, OUT] -> 2048 floats
    float* mask = out + B_ * OUT_;            // [B, 1, M]   -> 400000 floats

    cudaFuncSetAttribute(k1_gate, cudaFuncAttributeMaxDynamicSharedMemorySize, K1_SMEM);

    z_all<<<64, 256>>>();                                   // launch 1
    {
        dim3 grid(TILES_PER_B, B_);                         // launch 2
        k1_gate<<<grid, 256, K1_SMEM>>>(h, gsl1_w, gsl1_b, gsl2_w, gsl2_b);
    }
    {
        dim3 grid(16, B_);                                  // launch 3
        k2a<<<grid, 256>>>();
    }
    k2b<<<B_, 1024>>>(kptr);                                // launch 4 (profiled)
    {
        dim3 grid(16, B_);                                  // launch 5
        k2c<<<grid, 256>>>(mask);
    }
    {
        dim3 grid(64, B_);                                  // launch 6
        k4_selected<<<grid, 256>>>(h, att_w, att_b, w_w);
    }
    {
        dim3 grid(8, B_);                                   // launch 7
        k5a<<<grid, 256>>>(w_w, res_w, res_b);
    }
    k5b<<<B_, 256>>>(out);                                  // launch 8
}

// round 14
// speedup vs baseline: 1.0032x; 1.0022x over previous
#include <cuda_runtime.h>
#include <cuda_bf16.h>
#include <stdint.h>

// Problem constants (fixed by the dataset)
#define B_   8
#define M_   50000
#define D_   256
#define NH_  8
#define GH_  16
#define OUT_ 256
#define SEL_CAP 2048
#define CAND_CAP 4096
#define SEG_ 3125            // 50000 / 16

#define TILE_ROWS 512
#define TILES_PER_B 98               // ceil(50000/512)

// ---------------- scratch (device globals; no allocations) ----------------
__device__ __align__(16) float g_S[B_ * M_];
__device__ __align__(16) float g_colsum[B_ * D_];
__device__ float g_kth[B_];
__device__ int   g_selCount[B_];
__device__ int   g_selIdx[B_ * SEL_CAP];
__device__ __align__(16) float g_num[B_ * OUT_];
__device__ float g_den[B_ * NH_];
__device__ __align__(16) float g_v[B_ * OUT_];
__device__ unsigned g_hist2[B_ * 2048];
__device__ unsigned g_candCnt[B_];
__device__ float g_cand[B_ * CAND_CAP];

// ---------------- helpers ----------------
__device__ __forceinline__ unsigned keyOf(float x) {
    unsigned u = __float_as_uint(x);
    return (u & 0x80000000u) ? ~u : (u | 0x80000000u);
}
__device__ __forceinline__ float invKey(unsigned k) {
    unsigned u = (k & 0x80000000u) ? (k & 0x7FFFFFFFu) : ~k;
    return __uint_as_float(u);
}

// f32x2 packed FMA (Blackwell sm_103a)
#define FMA2(acc, a, b) asm("fma.rn.f32x2 %0, %1, %2, %0;" : "+l"(acc) : "l"(a), "l"(b))
__device__ __forceinline__ unsigned long long packdup(float x) {
    unsigned long long r;
    unsigned xu = __float_as_uint(x);
    asm("mov.b64 %0, {%1, %1};" : "=l"(r) : "r"(xu));
    return r;
}
__device__ __forceinline__ float f2lo(unsigned long long v) {
    return __uint_as_float((unsigned)(v & 0xFFFFFFFFu));
}
__device__ __forceinline__ float f2hi(unsigned long long v) {
    return __uint_as_float((unsigned)(v >> 32));
}

// ---------------- Z: zero all scratch (single launch) ----------------------
__global__ void z_all() {
    int i = blockIdx.x * 256 + threadIdx.x;   // grid 64 -> 16384 threads
    if (i < B_ * D_)   g_colsum[i] = 0.f;
    if (i < B_ * OUT_) g_num[i] = 0.f;
    if (i < B_ * 2048) g_hist2[i] = 0u;
    if (i < B_ * NH_)  g_den[i] = 0.f;
    if (i < B_) { g_selCount[i] = 0; g_candCnt[i] = 0u; }
}

// ---------------- K1: gate scores S + column sums (r7 known-good) ----------
__global__ __launch_bounds__(256, 3) void k1_gate(
    const float* __restrict__ h,
    const float* __restrict__ gsl1_w, const float* __restrict__ gsl1_b,
    const float* __restrict__ gsl2_w, const float* __restrict__ gsl2_b)
{
    extern __shared__ __align__(16) unsigned char smraw[];
    float4* st4 = (float4*)smraw;                                   // 512*8 float4 = 64KB
    unsigned long long* ws = (unsigned long long*)(smraw + 65536);  // 256 u64 = 2KB
    float* csum1 = (float*)(smraw + 65536 + 2048);                  // 256 f = 1KB

    const int tid  = threadIdx.x;
    const int b    = blockIdx.y;
    const int row0 = blockIdx.x * TILE_ROWS;
    const int hseg = tid & 3;
    const int rg   = tid >> 2;
    const int sw8  = tid & 7;
    const int q    = sw8 << 2;

    csum1[tid] = 0.f;

    const float* hb = h + (size_t)b * M_ * D_;
    const unsigned long long* gw = (const unsigned long long*)gsl1_w;

    unsigned long long acc[8][2];
#pragma unroll
    for (int r = 0; r < 8; r++) { acc[r][0] = 0ULL; acc[r][1] = 0ULL; }

    for (int ch = 0; ch < 8; ++ch) {
        const int c0 = ch * 32;
        __syncthreads();

        ws[tid] = gw[c0 * 8 + tid];

        float4 ca = make_float4(0.f, 0.f, 0.f, 0.f);
#pragma unroll
        for (int j = 0; j < 16; ++j) {
            int f = tid + 256 * j;
            int r = f >> 3;
            int gr = row0 + r;
            float4 v = make_float4(0.f, 0.f, 0.f, 0.f);
            if (gr < M_) v = *(const float4*)(hb + (size_t)gr * D_ + c0 + q);
            ca.x += v.x; ca.y += v.y; ca.z += v.z; ca.w += v.w;
            st4[r * 8 + (sw8 ^ ((r >> 3) & 7))] = v;
        }
        atomicAdd(&csum1[c0 + q + 0], ca.x);
        atomicAdd(&csum1[c0 + q + 1], ca.y);
        atomicAdd(&csum1[c0 + q + 2], ca.z);
        atomicAdd(&csum1[c0 + q + 3], ca.w);
        __syncthreads();

#pragma unroll
        for (int cg = 0; cg < 8; ++cg) {
            ulonglong2 w0 = *(const ulonglong2*)&ws[(cg * 4 + 0) * 8 + hseg * 2];
            ulonglong2 w1 = *(const ulonglong2*)&ws[(cg * 4 + 1) * 8 + hseg * 2];
            ulonglong2 w2 = *(const ulonglong2*)&ws[(cg * 4 + 2) * 8 + hseg * 2];
            ulonglong2 w3 = *(const ulonglong2*)&ws[(cg * 4 + 3) * 8 + hseg * 2];
            const int slot = cg ^ (rg & 7);
#pragma unroll
            for (int rr = 0; rr < 8; ++rr) {
                float4 x4 = st4[(rg * 8 + rr) * 8 + slot];
                unsigned long long xx;
                xx = packdup(x4.x); FMA2(acc[rr][0], xx, w0.x); FMA2(acc[rr][1], xx, w0.y);
                xx = packdup(x4.y); FMA2(acc[rr][0], xx, w1.x); FMA2(acc[rr][1], xx, w1.y);
                xx = packdup(x4.z); FMA2(acc[rr][0], xx, w2.x); FMA2(acc[rr][1], xx, w2.y);
                xx = packdup(x4.w); FMA2(acc[rr][0], xx, w3.x); FMA2(acc[rr][1], xx, w3.y);
            }
        }
    }
    __syncthreads();

    {
        const int u0 = 4 * hseg;
        const float b1a = gsl1_b[u0 + 0], b1b = gsl1_b[u0 + 1];
        const float b1c = gsl1_b[u0 + 2], b1d = gsl1_b[u0 + 3];
        const float w2a = gsl2_w[u0 + 0], w2b = gsl2_w[u0 + 1];
        const float w2c = gsl2_w[u0 + 2], w2d = gsl2_w[u0 + 3];

        float zr[8];
#pragma unroll
        for (int rr = 0; rr < 8; ++rr) {
            float z = 0.f;
            z = fmaf(fmaxf(f2lo(acc[rr][0]) + b1a, 0.f), w2a, z);
            z = fmaf(fmaxf(f2hi(acc[rr][0]) + b1b, 0.f), w2b, z);
            z = fmaf(fmaxf(f2lo(acc[rr][1]) + b1c, 0.f), w2c, z);
            z = fmaf(fmaxf(f2hi(acc[rr][1]) + b1d, 0.f), w2d, z);
            z += __shfl_xor_sync(0xFFFFFFFFu, z, 1);
            z += __shfl_xor_sync(0xFFFFFFFFu, z, 2);
            zr[rr] = z;
        }
        if (hseg == 0) {
            const float b2 = gsl2_b[0];
            const int base = row0 + rg * 8;
            if (base + 8 <= M_) {
                float4 s0, s1;
                s0.x = 1.0f / (1.0f + expf(-(zr[0] + b2)));
                s0.y = 1.0f / (1.0f + expf(-(zr[1] + b2)));
                s0.z = 1.0f / (1.0f + expf(-(zr[2] + b2)));
                s0.w = 1.0f / (1.0f + expf(-(zr[3] + b2)));
                s1.x = 1.0f / (1.0f + expf(-(zr[4] + b2)));
                s1.y = 1.0f / (1.0f + expf(-(zr[5] + b2)));
                s1.z = 1.0f / (1.0f + expf(-(zr[6] + b2)));
                s1.w = 1.0f / (1.0f + expf(-(zr[7] + b2)));
                *(float4*)&g_S[(size_t)b * M_ + base] = s0;
                *(float4*)&g_S[(size_t)b * M_ + base + 4] = s1;
            }
        }
    }

    atomicAdd(&g_colsum[b * D_ + tid], csum1[tid]);
}

// ---------------- K2a: parallel top-11-bit histogram of S ------------------
__global__ __launch_bounds__(256) void k2a() {
    const int b = blockIdx.y, seg = blockIdx.x;   // (16, B_)
    const int tid = threadIdx.x;
    __shared__ unsigned hist[2048];
    for (int i = tid; i < 2048; i += 256) hist[i] = 0u;
    __syncthreads();
    const float* Sb = &g_S[(size_t)b * M_];
    const int lo = seg * SEG_, hi = lo + SEG_;
    for (int i = lo + tid; i < hi; i += 256)
        atomicAdd(&hist[keyOf(Sb[i]) >> 21], 1u);
    __syncthreads();
    for (int i = tid; i < 2048; i += 256)
        if (hist[i]) atomicAdd(&g_hist2[b * 2048 + i], hist[i]);
}

// ---------------- parallel bin pick (block-wide, from shared hist) ---------
// 32 warps each reduce a group of NBINS/32 bins; thread 0 then walks only
// 32 group sums + NBINS/32 in-group bins serially from shared.
// Result in sOut[0]=bin, sOut[1]=remaining need within bin.
template<int NBINS>
__device__ __forceinline__ void pick_bin(const unsigned* hist, unsigned need_in,
                                         unsigned* sGsum, unsigned* sOut)
{
    const int tid = threadIdx.x;
    const int w = tid >> 5, l = tid & 31;
    constexpr int GS = NBINS / 32;
    unsigned s = 0;
#pragma unroll
    for (int i = l; i < GS; i += 32) s += hist[w * GS + i];
#pragma unroll
    for (int m = 16; m; m >>= 1) s += __shfl_xor_sync(0xFFFFFFFFu, s, m);
    if (l == 0) sGsum[w] = s;
    __syncthreads();
    if (tid == 0) {
        unsigned need = need_in, cum = 0;
        int g = 0;
        for (int v = 31; v >= 0; --v) {
            unsigned c = sGsum[v];
            if (cum + c >= need) { g = v; need -= cum; break; }
            cum += c;
        }
        cum = 0;
        int bin = g * GS;
        for (int v = GS - 1; v >= 0; --v) {
            unsigned c = hist[g * GS + v];
            if (cum + c >= need) { bin = g * GS + v; need -= cum; break; }
            cum += c;
        }
        sOut[0] = (unsigned)bin; sOut[1] = need;
    }
    __syncthreads();
}

// ---------------- K2b: refine to exact k-th (1 block / batch) -------------
__global__ __launch_bounds__(1024) void k2b(const int* __restrict__ kptr) {
    const int b = blockIdx.x;
    const int tid = threadIdx.x;
    __shared__ unsigned hist[2048];
    __shared__ unsigned sGsum[32];
    __shared__ unsigned sOut[2];

    int kk = kptr ? *kptr : 500;
    if (kk <= 0 || kk > M_) {
        float kf = __int_as_float(kk);
        if (kf >= 1.f && kf <= (float)M_) kk = (int)kf;
        else kk = kk < 1 ? 1 : M_;
    }
    if (kk > M_) kk = M_;

    // level A: stage global histogram to shared, parallel pick
    for (int i = tid; i < 2048; i += 1024) hist[i] = g_hist2[b * 2048 + i];
    __syncthreads();
    pick_bin<2048>(hist, (unsigned)kk, sGsum, sOut);
    const unsigned binA = sOut[0];
    unsigned needB = sOut[1];
    __syncthreads();

    for (int i = tid; i < 2048; i += 1024) hist[i] = 0u;
    __syncthreads();

    // level B: one full scan — histogram bits [10,21) of bin-A matches,
    // compact survivor values into g_cand
    const float* Sb = &g_S[(size_t)b * M_];
    for (int i = tid; i < M_; i += 1024) {
        float s = Sb[i];
        unsigned key = keyOf(s);
        if ((key >> 21) == binA) {
            atomicAdd(&hist[(key >> 10) & 0x7FFu], 1u);
            unsigned p = atomicAdd(&g_candCnt[b], 1u);
            if (p < CAND_CAP) g_cand[b * CAND_CAP + p] = s;
        }
    }
    __syncthreads();
    pick_bin<2048>(hist, needB, sGsum, sOut);
    const unsigned prefAB = (binA << 21) | (sOut[0] << 10);
    const unsigned needC = sOut[1];
    __syncthreads();

    for (int i = tid; i < 1024; i += 1024) hist[i] = 0u;
    __syncthreads();

    // level C: last 10 bits from candidates (or full-scan fallback)
    const unsigned cnt = atomicAdd(&g_candCnt[b], 0u);
    if (cnt <= CAND_CAP) {
        for (unsigned i = tid; i < cnt; i += 1024) {
            unsigned key = keyOf(g_cand[b * CAND_CAP + i]);
            if ((key >> 10) == (prefAB >> 10)) atomicAdd(&hist[key & 0x3FFu], 1u);
        }
    } else {
        for (int i = tid; i < M_; i += 1024) {
            unsigned key = keyOf(Sb[i]);
            if ((key >> 10) == (prefAB >> 10)) atomicAdd(&hist[key & 0x3FFu], 1u);
        }
    }
    __syncthreads();
    pick_bin<1024>(hist, needC, sGsum, sOut);
    if (tid == 0) g_kth[b] = invKey(prefAB | sOut[0]);
}

// ---------------- K2c: parallel mask + gather ------------------------------
__global__ __launch_bounds__(256) void k2c(float* __restrict__ outmask) {
    const int b = blockIdx.y, seg = blockIdx.x;   // (16, B_)
    const float kth = g_kth[b];
    const int lo = seg * SEG_, hi = lo + SEG_;
    for (int i = lo + threadIdx.x; i < hi; i += 256) {
        float s = g_S[(size_t)b * M_ + i];
        bool sel = s >= kth;
        outmask[b * M_ + i] = sel ? 1.f : 0.f;
        if (sel) {
            int pos = atomicAdd(&g_selCount[b], 1);
            if (pos < SEL_CAP) g_selIdx[b * SEL_CAP + pos] = i;
        }
    }
}

// ---------------- K4: selected-row correction (num / den) -----------------
#define RS 16
__global__ __launch_bounds__(256) void k4_selected(
    const float* __restrict__ h,
    const float* __restrict__ att_w, const float* __restrict__ att_b,
    const float* __restrict__ w_w)
{
    __shared__ __align__(16) float hsh[RS][D_];
    __shared__ float efac[RS][NH_];
    __shared__ float aw[D_ * NH_];

    const int b = blockIdx.y;
    const int tid = threadIdx.x;
    for (int i = tid; i < D_ * NH_; i += 256) aw[i] = att_w[i];

    int cnt = g_selCount[b];
    if (cnt > SEL_CAP) cnt = SEL_CAP;
    const int ngroups = (cnt + RS - 1) / RS;
    const float* hb = h + (size_t)b * M_ * D_;

    for (int g = blockIdx.x; g < ngroups; g += gridDim.x) {
        __syncthreads();
        for (int i = tid; i < RS * (D_ / 4); i += 256) {
            int r = i >> 6, c4 = (i & 63) << 2;
            int si = g * RS + r;
            float4 v = make_float4(0.f, 0.f, 0.f, 0.f);
            if (si < cnt)
                v = *(const float4*)(hb + (size_t)g_selIdx[b * SEL_CAP + si] * D_ + c4);
            *(float4*)&hsh[r][c4] = v;
        }
        __syncthreads();
        if (tid < RS * NH_) {
            int r = tid >> 3, hd = tid & 7;
            float s = 0.f;
            for (int c = 0; c < D_; c++) s = fmaf(hsh[r][c], aw[c * NH_ + hd], s);
            float a = fmaxf(s + att_b[hd], 0.f);
            efac[r][hd] = (g * RS + r < cnt) ? (expf(a) - 1.f) : 0.f;
        }
        __syncthreads();

        const int e = tid;
        float acc[RS];
#pragma unroll
        for (int r = 0; r < RS; r++) acc[r] = 0.f;
        for (int c4 = 0; c4 < D_; c4 += 4) {
            float w0 = __ldg(&w_w[(c4 + 0) * OUT_ + e]);
            float w1 = __ldg(&w_w[(c4 + 1) * OUT_ + e]);
            float w2 = __ldg(&w_w[(c4 + 2) * OUT_ + e]);
            float w3 = __ldg(&w_w[(c4 + 3) * OUT_ + e]);
#pragma unroll
            for (int r = 0; r < RS; r++) {
                float4 hv = *(const float4*)&hsh[r][c4];
                float a = acc[r];
                a = fmaf(hv.x, w0, a);
                a = fmaf(hv.y, w1, a);
                a = fmaf(hv.z, w2, a);
                a = fmaf(hv.w, w3, a);
                acc[r] = a;
            }
        }
        const int hd = e >> 5;
        float s = 0.f;
#pragma unroll
        for (int r = 0; r < RS; r++) s = fmaf(efac[r][hd], acc[r], s);
        atomicAdd(&g_num[b * OUT_ + e], s);
        if (tid < NH_) {
            float d = 0.f;
#pragma unroll
            for (int r = 0; r < RS; r++) d += efac[r][tid];
            atomicAdd(&g_den[b * NH_ + tid], d);
        }
    }
}

// ---------------- K5a: base term + Q_res + combine (col-parallel) ---------
__global__ __launch_bounds__(256) void k5a(
    const float* __restrict__ w_w,
    const float* __restrict__ res_w, const float* __restrict__ res_b)
{
    const int b = blockIdx.y;
    const int e = blockIdx.x * 32 + (threadIdx.x >> 3);
    const int l8 = threadIdx.x & 7;
    __shared__ float cs[D_];
    cs[threadIdx.x] = g_colsum[b * D_ + threadIdx.x];
    __syncthreads();

    float base = 0.f, qr = 0.f;
#pragma unroll 8
    for (int i = 0; i < 32; i++) {
        int c = l8 + 8 * i;
        float x = cs[c];
        base = fmaf(x, __ldg(&w_w[c * OUT_ + e]), base);
        qr   = fmaf(x, __ldg(&res_w[c * OUT_ + e]), qr);
    }
#pragma unroll
    for (int m = 1; m < 8; m <<= 1) {
        base += __shfl_xor_sync(0xFFFFFFFFu, base, m);
        qr   += __shfl_xor_sync(0xFFFFFFFFu, qr, m);
    }
    if (l8 == 0) {
        float Qres = fmaxf(qr * (1.0f / (float)M_) + res_b[e], 0.f);
        float den = (float)M_ + g_den[b * NH_ + (e >> 5)];
        float ov = (base + g_num[b * OUT_ + e]) / den;
        g_v[b * OUT_ + e] = fmaxf(ov + Qres, 0.f);
    }
}

// ---------------- K5b: layernorm of the 256-vector ------------------------
__global__ __launch_bounds__(256) void k5b(float* __restrict__ out)
{
    const int b = blockIdx.x;
    const int e = threadIdx.x;
    __shared__ float red[256];

    float v = g_v[b * OUT_ + e];
    red[e] = v; __syncthreads();
    for (int s = 128; s > 0; s >>= 1) {
        if (e < s) red[e] += red[e + s];
        __syncthreads();
    }
    float mean = red[0] * (1.0f / 256.0f);
    __syncthreads();
    float dm = v - mean;
    red[e] = dm * dm; __syncthreads();
    for (int s = 128; s > 0; s >>= 1) {
        if (e < s) red[e] += red[e + s];
        __syncthreads();
    }
    float var = red[0] * (1.0f / 256.0f);
    out[b * OUT_ + e] = dm * rsqrtf(var + 1e-8f);
}

// ---------------- launch -----------------
#define K1_SMEM (65536 + 2048 + 1024)

extern "C" void kernel_launch(void* const* d_in, const int* in_sizes, int n_in,
                              void* d_out, int out_size)
{
    const float* h      = (const float*)d_in[0];
    const float* att_w  = (const float*)d_in[1];
    const float* att_b  = (const float*)d_in[2];
    const float* w_w    = (const float*)d_in[3];
    const float* res_w  = (const float*)d_in[4];
    const float* res_b  = (const float*)d_in[5];
    const float* gsl1_w = (const float*)d_in[6];
    const float* gsl1_b = (const float*)d_in[7];
    const float* gsl2_w = (const float*)d_in[8];
    const float* gsl2_b = (const float*)d_in[9];
    const int*   kptr   = (n_in > 10) ? (const int*)d_in[10] : nullptr;

    float* out  = (float*)d_out;              // [B, 1, OUT] -> 2048 floats
    float* mask = out + B_ * OUT_;            // [B, 1, M]   -> 400000 floats

    cudaFuncSetAttribute(k1_gate, cudaFuncAttributeMaxDynamicSharedMemorySize, K1_SMEM);

    z_all<<<64, 256>>>();                                   // launch 1
    {
        dim3 grid(TILES_PER_B, B_);                         // launch 2
        k1_gate<<<grid, 256, K1_SMEM>>>(h, gsl1_w, gsl1_b, gsl2_w, gsl2_b);
    }
    {
        dim3 grid(16, B_);                                  // launch 3
        k2a<<<grid, 256>>>();
    }
    k2b<<<B_, 1024>>>(kptr);                                // launch 4 (profiled)
    {
        dim3 grid(16, B_);                                  // launch 5
        k2c<<<grid, 256>>>(mask);
    }
    {
        dim3 grid(64, B_);                                  // launch 6
        k4_selected<<<grid, 256>>>(h, att_w, att_b, w_w);
    }
    {
        dim3 grid(8, B_);                                   // launch 7
        k5a<<<grid, 256>>>(w_w, res_w, res_b);
    }
    k5b<<<B_, 256>>>(out);                                  // launch 8
}

// round 15
// speedup vs baseline: 1.0897x; 1.0861x over previous
#include <cuda_runtime.h>
#include <cuda_bf16.h>
#include <stdint.h>

// Problem constants (fixed by the dataset)
#define B_   8
#define M_   50000
#define D_   256
#define NH_  8
#define GH_  16
#define OUT_ 256
#define SEL_CAP 2048
#define CAND_CAP 4096
#define SEG_ 3125            // 50000 / 16

#define TILE_ROWS 512
#define TILES_PER_B 98               // ceil(50000/512)

// ---------------- scratch (device globals; no allocations) ----------------
__device__ __align__(16) float g_S[B_ * M_];
__device__ __align__(16) float g_colsum[B_ * D_];
__device__ float g_kth[B_];
__device__ int   g_selCount[B_];
__device__ int   g_selIdx[B_ * SEL_CAP];
__device__ __align__(16) float g_num[B_ * OUT_];
__device__ float g_den[B_ * NH_];
__device__ __align__(16) float g_v[B_ * OUT_];
__device__ unsigned g_hist2[B_ * 2048];
__device__ unsigned g_histB[B_ * 2048];
__device__ unsigned g_binA[B_];
__device__ unsigned g_needB[B_];
__device__ unsigned g_candCnt[B_];
__device__ float g_cand[B_ * CAND_CAP];

// ---------------- helpers ----------------
__device__ __forceinline__ unsigned keyOf(float x) {
    unsigned u = __float_as_uint(x);
    return (u & 0x80000000u) ? ~u : (u | 0x80000000u);
}
__device__ __forceinline__ float invKey(unsigned k) {
    unsigned u = (k & 0x80000000u) ? (k & 0x7FFFFFFFu) : ~k;
    return __uint_as_float(u);
}

// f32x2 packed FMA (Blackwell sm_103a)
#define FMA2(acc, a, b) asm("fma.rn.f32x2 %0, %1, %2, %0;" : "+l"(acc) : "l"(a), "l"(b))
__device__ __forceinline__ unsigned long long packdup(float x) {
    unsigned long long r;
    unsigned xu = __float_as_uint(x);
    asm("mov.b64 %0, {%1, %1};" : "=l"(r) : "r"(xu));
    return r;
}
__device__ __forceinline__ float f2lo(unsigned long long v) {
    return __uint_as_float((unsigned)(v & 0xFFFFFFFFu));
}
__device__ __forceinline__ float f2hi(unsigned long long v) {
    return __uint_as_float((unsigned)(v >> 32));
}

// ---------------- Z: zero all scratch (single launch) ----------------------
__global__ void z_all() {
    int i = blockIdx.x * 256 + threadIdx.x;   // grid 64 -> 16384 threads
    if (i < B_ * D_)   g_colsum[i] = 0.f;
    if (i < B_ * OUT_) g_num[i] = 0.f;
    if (i < B_ * 2048) { g_hist2[i] = 0u; g_histB[i] = 0u; }
    if (i < B_ * NH_)  g_den[i] = 0.f;
    if (i < B_) { g_selCount[i] = 0; g_candCnt[i] = 0u; }
}

// ---------------- K1: gate scores S + column sums (r7 known-good) ----------
__global__ __launch_bounds__(256, 3) void k1_gate(
    const float* __restrict__ h,
    const float* __restrict__ gsl1_w, const float* __restrict__ gsl1_b,
    const float* __restrict__ gsl2_w, const float* __restrict__ gsl2_b)
{
    extern __shared__ __align__(16) unsigned char smraw[];
    float4* st4 = (float4*)smraw;                                   // 512*8 float4 = 64KB
    unsigned long long* ws = (unsigned long long*)(smraw + 65536);  // 256 u64 = 2KB
    float* csum1 = (float*)(smraw + 65536 + 2048);                  // 256 f = 1KB

    const int tid  = threadIdx.x;
    const int b    = blockIdx.y;
    const int row0 = blockIdx.x * TILE_ROWS;
    const int hseg = tid & 3;
    const int rg   = tid >> 2;
    const int sw8  = tid & 7;
    const int q    = sw8 << 2;

    csum1[tid] = 0.f;

    const float* hb = h + (size_t)b * M_ * D_;
    const unsigned long long* gw = (const unsigned long long*)gsl1_w;

    unsigned long long acc[8][2];
#pragma unroll
    for (int r = 0; r < 8; r++) { acc[r][0] = 0ULL; acc[r][1] = 0ULL; }

    for (int ch = 0; ch < 8; ++ch) {
        const int c0 = ch * 32;
        __syncthreads();

        ws[tid] = gw[c0 * 8 + tid];

        float4 ca = make_float4(0.f, 0.f, 0.f, 0.f);
#pragma unroll
        for (int j = 0; j < 16; ++j) {
            int f = tid + 256 * j;
            int r = f >> 3;
            int gr = row0 + r;
            float4 v = make_float4(0.f, 0.f, 0.f, 0.f);
            if (gr < M_) v = *(const float4*)(hb + (size_t)gr * D_ + c0 + q);
            ca.x += v.x; ca.y += v.y; ca.z += v.z; ca.w += v.w;
            st4[r * 8 + (sw8 ^ ((r >> 3) & 7))] = v;
        }
        atomicAdd(&csum1[c0 + q + 0], ca.x);
        atomicAdd(&csum1[c0 + q + 1], ca.y);
        atomicAdd(&csum1[c0 + q + 2], ca.z);
        atomicAdd(&csum1[c0 + q + 3], ca.w);
        __syncthreads();

#pragma unroll
        for (int cg = 0; cg < 8; ++cg) {
            ulonglong2 w0 = *(const ulonglong2*)&ws[(cg * 4 + 0) * 8 + hseg * 2];
            ulonglong2 w1 = *(const ulonglong2*)&ws[(cg * 4 + 1) * 8 + hseg * 2];
            ulonglong2 w2 = *(const ulonglong2*)&ws[(cg * 4 + 2) * 8 + hseg * 2];
            ulonglong2 w3 = *(const ulonglong2*)&ws[(cg * 4 + 3) * 8 + hseg * 2];
            const int slot = cg ^ (rg & 7);
#pragma unroll
            for (int rr = 0; rr < 8; ++rr) {
                float4 x4 = st4[(rg * 8 + rr) * 8 + slot];
                unsigned long long xx;
                xx = packdup(x4.x); FMA2(acc[rr][0], xx, w0.x); FMA2(acc[rr][1], xx, w0.y);
                xx = packdup(x4.y); FMA2(acc[rr][0], xx, w1.x); FMA2(acc[rr][1], xx, w1.y);
                xx = packdup(x4.z); FMA2(acc[rr][0], xx, w2.x); FMA2(acc[rr][1], xx, w2.y);
                xx = packdup(x4.w); FMA2(acc[rr][0], xx, w3.x); FMA2(acc[rr][1], xx, w3.y);
            }
        }
    }
    __syncthreads();

    {
        const int u0 = 4 * hseg;
        const float b1a = gsl1_b[u0 + 0], b1b = gsl1_b[u0 + 1];
        const float b1c = gsl1_b[u0 + 2], b1d = gsl1_b[u0 + 3];
        const float w2a = gsl2_w[u0 + 0], w2b = gsl2_w[u0 + 1];
        const float w2c = gsl2_w[u0 + 2], w2d = gsl2_w[u0 + 3];

        float zr[8];
#pragma unroll
        for (int rr = 0; rr < 8; ++rr) {
            float z = 0.f;
            z = fmaf(fmaxf(f2lo(acc[rr][0]) + b1a, 0.f), w2a, z);
            z = fmaf(fmaxf(f2hi(acc[rr][0]) + b1b, 0.f), w2b, z);
            z = fmaf(fmaxf(f2lo(acc[rr][1]) + b1c, 0.f), w2c, z);
            z = fmaf(fmaxf(f2hi(acc[rr][1]) + b1d, 0.f), w2d, z);
            z += __shfl_xor_sync(0xFFFFFFFFu, z, 1);
            z += __shfl_xor_sync(0xFFFFFFFFu, z, 2);
            zr[rr] = z;
        }
        if (hseg == 0) {
            const float b2 = gsl2_b[0];
            const int base = row0 + rg * 8;
            if (base + 8 <= M_) {
                float4 s0, s1;
                s0.x = 1.0f / (1.0f + expf(-(zr[0] + b2)));
                s0.y = 1.0f / (1.0f + expf(-(zr[1] + b2)));
                s0.z = 1.0f / (1.0f + expf(-(zr[2] + b2)));
                s0.w = 1.0f / (1.0f + expf(-(zr[3] + b2)));
                s1.x = 1.0f / (1.0f + expf(-(zr[4] + b2)));
                s1.y = 1.0f / (1.0f + expf(-(zr[5] + b2)));
                s1.z = 1.0f / (1.0f + expf(-(zr[6] + b2)));
                s1.w = 1.0f / (1.0f + expf(-(zr[7] + b2)));
                *(float4*)&g_S[(size_t)b * M_ + base] = s0;
                *(float4*)&g_S[(size_t)b * M_ + base + 4] = s1;
            }
        }
    }

    atomicAdd(&g_colsum[b * D_ + tid], csum1[tid]);
}

// ---------------- K2a: parallel top-11-bit histogram of S ------------------
__global__ __launch_bounds__(256) void k2a() {
    const int b = blockIdx.y, seg = blockIdx.x;   // (16, B_)
    const int tid = threadIdx.x;
    __shared__ unsigned hist[2048];
    for (int i = tid; i < 2048; i += 256) hist[i] = 0u;
    __syncthreads();
    const float* Sb = &g_S[(size_t)b * M_];
    const int lo = seg * SEG_, hi = lo + SEG_;
    for (int i = lo + tid; i < hi; i += 256)
        atomicAdd(&hist[keyOf(Sb[i]) >> 21], 1u);
    __syncthreads();
    for (int i = tid; i < 2048; i += 256)
        if (hist[i]) atomicAdd(&g_hist2[b * 2048 + i], hist[i]);
}

// ---------------- parallel bin pick (block-wide, from shared hist) ---------
// Requires blockDim.x == 1024. 32 warps each reduce NBINS/32 bins; thread 0
// walks 32 group sums + NBINS/32 in-group bins from shared.
template<int NBINS>
__device__ __forceinline__ void pick_bin(const unsigned* hist, unsigned need_in,
                                         unsigned* sGsum, unsigned* sOut)
{
    const int tid = threadIdx.x;
    const int w = tid >> 5, l = tid & 31;
    constexpr int GS = NBINS / 32;
    unsigned s = 0;
#pragma unroll
    for (int i = l; i < GS; i += 32) s += hist[w * GS + i];
#pragma unroll
    for (int m = 16; m; m >>= 1) s += __shfl_xor_sync(0xFFFFFFFFu, s, m);
    if (l == 0) sGsum[w] = s;
    __syncthreads();
    if (tid == 0) {
        unsigned need = need_in, cum = 0;
        int g = 0;
        for (int v = 31; v >= 0; --v) {
            unsigned c = sGsum[v];
            if (cum + c >= need) { g = v; need -= cum; break; }
            cum += c;
        }
        cum = 0;
        int bin = g * GS;
        for (int v = GS - 1; v >= 0; --v) {
            unsigned c = hist[g * GS + v];
            if (cum + c >= need) { bin = g * GS + v; need -= cum; break; }
            cum += c;
        }
        sOut[0] = (unsigned)bin; sOut[1] = need;
    }
    __syncthreads();
}

// ---------------- K2b1: pick level-A bin (tiny) ----------------------------
__global__ __launch_bounds__(1024) void k2b1(const int* __restrict__ kptr) {
    const int b = blockIdx.x;
    const int tid = threadIdx.x;
    __shared__ unsigned hist[2048];
    __shared__ unsigned sGsum[32];
    __shared__ unsigned sOut[2];

    int kk = kptr ? *kptr : 500;
    if (kk <= 0 || kk > M_) {
        float kf = __int_as_float(kk);
        if (kf >= 1.f && kf <= (float)M_) kk = (int)kf;
        else kk = kk < 1 ? 1 : M_;
    }
    if (kk > M_) kk = M_;

    for (int i = tid; i < 2048; i += 1024) hist[i] = g_hist2[b * 2048 + i];
    __syncthreads();
    pick_bin<2048>(hist, (unsigned)kk, sGsum, sOut);
    if (tid == 0) { g_binA[b] = sOut[0]; g_needB[b] = sOut[1]; }
}

// ---------------- K2b2: parallel level-B scan (chip-wide) ------------------
// histogram bits [10,21) among bin-A matches; compact survivor values.
__global__ __launch_bounds__(256) void k2b2() {
    const int b = blockIdx.y, seg = blockIdx.x;   // (16, B_)
    const int tid = threadIdx.x;
    __shared__ unsigned hist[2048];
    for (int i = tid; i < 2048; i += 256) hist[i] = 0u;
    __syncthreads();

    const unsigned binA = g_binA[b];
    const float* Sb = &g_S[(size_t)b * M_];
    const int lo = seg * SEG_, hi = lo + SEG_;
    for (int i = lo + tid; i < hi; i += 256) {
        float s = Sb[i];
        unsigned key = keyOf(s);
        if ((key >> 21) == binA) {
            atomicAdd(&hist[(key >> 10) & 0x7FFu], 1u);
            unsigned p = atomicAdd(&g_candCnt[b], 1u);
            if (p < CAND_CAP) g_cand[b * CAND_CAP + p] = s;
        }
    }
    __syncthreads();
    for (int i = tid; i < 2048; i += 256)
        if (hist[i]) atomicAdd(&g_histB[b * 2048 + i], hist[i]);
}

// ---------------- K2b3: pick level-B bin + level C from candidates ---------
__global__ __launch_bounds__(1024) void k2b3() {
    const int b = blockIdx.x;
    const int tid = threadIdx.x;
    __shared__ unsigned hist[2048];
    __shared__ unsigned sGsum[32];
    __shared__ unsigned sOut[2];

    for (int i = tid; i < 2048; i += 1024) hist[i] = g_histB[b * 2048 + i];
    __syncthreads();
    pick_bin<2048>(hist, g_needB[b], sGsum, sOut);
    const unsigned prefAB = (g_binA[b] << 21) | (sOut[0] << 10);
    const unsigned needC = sOut[1];
    __syncthreads();

    for (int i = tid; i < 1024; i += 1024) hist[i] = 0u;
    __syncthreads();

    const unsigned cnt = g_candCnt[b];
    if (cnt <= CAND_CAP) {
        for (unsigned i = tid; i < cnt; i += 1024) {
            unsigned key = keyOf(g_cand[b * CAND_CAP + i]);
            if ((key >> 10) == (prefAB >> 10)) atomicAdd(&hist[key & 0x3FFu], 1u);
        }
    } else {
        const float* Sb = &g_S[(size_t)b * M_];
        for (int i = tid; i < M_; i += 1024) {
            unsigned key = keyOf(Sb[i]);
            if ((key >> 10) == (prefAB >> 10)) atomicAdd(&hist[key & 0x3FFu], 1u);
        }
    }
    __syncthreads();
    pick_bin<1024>(hist, needC, sGsum, sOut);
    if (tid == 0) g_kth[b] = invKey(prefAB | sOut[0]);
}

// ---------------- K2c: parallel mask + gather ------------------------------
__global__ __launch_bounds__(256) void k2c(float* __restrict__ outmask) {
    const int b = blockIdx.y, seg = blockIdx.x;   // (16, B_)
    const float kth = g_kth[b];
    const int lo = seg * SEG_, hi = lo + SEG_;
    for (int i = lo + threadIdx.x; i < hi; i += 256) {
        float s = g_S[(size_t)b * M_ + i];
        bool sel = s >= kth;
        outmask[b * M_ + i] = sel ? 1.f : 0.f;
        if (sel) {
            int pos = atomicAdd(&g_selCount[b], 1);
            if (pos < SEL_CAP) g_selIdx[b * SEL_CAP + pos] = i;
        }
    }
}

// ---------------- K4: selected-row correction (num / den) -----------------
#define RS 16
__global__ __launch_bounds__(256) void k4_selected(
    const float* __restrict__ h,
    const float* __restrict__ att_w, const float* __restrict__ att_b,
    const float* __restrict__ w_w)
{
    __shared__ __align__(16) float hsh[RS][D_];
    __shared__ float efac[RS][NH_];
    __shared__ float aw[D_ * NH_];

    const int b = blockIdx.y;
    const int tid = threadIdx.x;
    for (int i = tid; i < D_ * NH_; i += 256) aw[i] = att_w[i];

    int cnt = g_selCount[b];
    if (cnt > SEL_CAP) cnt = SEL_CAP;
    const int ngroups = (cnt + RS - 1) / RS;
    const float* hb = h + (size_t)b * M_ * D_;

    for (int g = blockIdx.x; g < ngroups; g += gridDim.x) {
        __syncthreads();
        for (int i = tid; i < RS * (D_ / 4); i += 256) {
            int r = i >> 6, c4 = (i & 63) << 2;
            int si = g * RS + r;
            float4 v = make_float4(0.f, 0.f, 0.f, 0.f);
            if (si < cnt)
                v = *(const float4*)(hb + (size_t)g_selIdx[b * SEL_CAP + si] * D_ + c4);
            *(float4*)&hsh[r][c4] = v;
        }
        __syncthreads();
        if (tid < RS * NH_) {
            int r = tid >> 3, hd = tid & 7;
            float s = 0.f;
            for (int c = 0; c < D_; c++) s = fmaf(hsh[r][c], aw[c * NH_ + hd], s);
            float a = fmaxf(s + att_b[hd], 0.f);
            efac[r][hd] = (g * RS + r < cnt) ? (expf(a) - 1.f) : 0.f;
        }
        __syncthreads();

        const int e = tid;
        float acc[RS];
#pragma unroll
        for (int r = 0; r < RS; r++) acc[r] = 0.f;
        for (int c4 = 0; c4 < D_; c4 += 4) {
            float w0 = __ldg(&w_w[(c4 + 0) * OUT_ + e]);
            float w1 = __ldg(&w_w[(c4 + 1) * OUT_ + e]);
            float w2 = __ldg(&w_w[(c4 + 2) * OUT_ + e]);
            float w3 = __ldg(&w_w[(c4 + 3) * OUT_ + e]);
#pragma unroll
            for (int r = 0; r < RS; r++) {
                float4 hv = *(const float4*)&hsh[r][c4];
                float a = acc[r];
                a = fmaf(hv.x, w0, a);
                a = fmaf(hv.y, w1, a);
                a = fmaf(hv.z, w2, a);
                a = fmaf(hv.w, w3, a);
                acc[r] = a;
            }
        }
        const int hd = e >> 5;
        float s = 0.f;
#pragma unroll
        for (int r = 0; r < RS; r++) s = fmaf(efac[r][hd], acc[r], s);
        atomicAdd(&g_num[b * OUT_ + e], s);
        if (tid < NH_) {
            float d = 0.f;
#pragma unroll
            for (int r = 0; r < RS; r++) d += efac[r][tid];
            atomicAdd(&g_den[b * NH_ + tid], d);
        }
    }
}

// ---------------- K5a: base term + Q_res + combine (col-parallel) ---------
__global__ __launch_bounds__(256) void k5a(
    const float* __restrict__ w_w,
    const float* __restrict__ res_w, const float* __restrict__ res_b)
{
    const int b = blockIdx.y;
    const int e = blockIdx.x * 32 + (threadIdx.x >> 3);
    const int l8 = threadIdx.x & 7;
    __shared__ float cs[D_];
    cs[threadIdx.x] = g_colsum[b * D_ + threadIdx.x];
    __syncthreads();

    float base = 0.f, qr = 0.f;
#pragma unroll 8
    for (int i = 0; i < 32; i++) {
        int c = l8 + 8 * i;
        float x = cs[c];
        base = fmaf(x, __ldg(&w_w[c * OUT_ + e]), base);
        qr   = fmaf(x, __ldg(&res_w[c * OUT_ + e]), qr);
    }
#pragma unroll
    for (int m = 1; m < 8; m <<= 1) {
        base += __shfl_xor_sync(0xFFFFFFFFu, base, m);
        qr   += __shfl_xor_sync(0xFFFFFFFFu, qr, m);
    }
    if (l8 == 0) {
        float Qres = fmaxf(qr * (1.0f / (float)M_) + res_b[e], 0.f);
        float den = (float)M_ + g_den[b * NH_ + (e >> 5)];
        float ov = (base + g_num[b * OUT_ + e]) / den;
        g_v[b * OUT_ + e] = fmaxf(ov + Qres, 0.f);
    }
}

// ---------------- K5b: layernorm of the 256-vector ------------------------
__global__ __launch_bounds__(256) void k5b(float* __restrict__ out)
{
    const int b = blockIdx.x;
    const int e = threadIdx.x;
    __shared__ float red[256];

    float v = g_v[b * OUT_ + e];
    red[e] = v; __syncthreads();
    for (int s = 128; s > 0; s >>= 1) {
        if (e < s) red[e] += red[e + s];
        __syncthreads();
    }
    float mean = red[0] * (1.0f / 256.0f);
    __syncthreads();
    float dm = v - mean;
    red[e] = dm * dm; __syncthreads();
    for (int s = 128; s > 0; s >>= 1) {
        if (e < s) red[e] += red[e + s];
        __syncthreads();
    }
    float var = red[0] * (1.0f / 256.0f);
    out[b * OUT_ + e] = dm * rsqrtf(var + 1e-8f);
}

// ---------------- launch -----------------
#define K1_SMEM (65536 + 2048 + 1024)

extern "C" void kernel_launch(void* const* d_in, const int* in_sizes, int n_in,
                              void* d_out, int out_size)
{
    const float* h      = (const float*)d_in[0];
    const float* att_w  = (const float*)d_in[1];
    const float* att_b  = (const float*)d_in[2];
    const float* w_w    = (const float*)d_in[3];
    const float* res_w  = (const float*)d_in[4];
    const float* res_b  = (const float*)d_in[5];
    const float* gsl1_w = (const float*)d_in[6];
    const float* gsl1_b = (const float*)d_in[7];
    const float* gsl2_w = (const float*)d_in[8];
    const float* gsl2_b = (const float*)d_in[9];
    const int*   kptr   = (n_in > 10) ? (const int*)d_in[10] : nullptr;

    float* out  = (float*)d_out;              // [B, 1, OUT] -> 2048 floats
    float* mask = out + B_ * OUT_;            // [B, 1, M]   -> 400000 floats

    cudaFuncSetAttribute(k1_gate, cudaFuncAttributeMaxDynamicSharedMemorySize, K1_SMEM);

    z_all<<<64, 256>>>();                                   // launch 1
    {
        dim3 grid(TILES_PER_B, B_);                         // launch 2
        k1_gate<<<grid, 256, K1_SMEM>>>(h, gsl1_w, gsl1_b, gsl2_w, gsl2_b);
    }
    {
        dim3 grid(16, B_);                                  // launch 3
        k2a<<<grid, 256>>>();
    }
    k2b1<<<B_, 1024>>>(kptr);                               // launch 4 (profiled)
    {
        dim3 grid(16, B_);                                  // launch 5
        k2b2<<<grid, 256>>>();
    }
    k2b3<<<B_, 1024>>>();                                   // launch 6
    {
        dim3 grid(16, B_);                                  // launch 7
        k2c<<<grid, 256>>>(mask);
    }
    {
        dim3 grid(64, B_);                                  // launch 8
        k4_selected<<<grid, 256>>>(h, att_w, att_b, w_w);
    }
    {
        dim3 grid(8, B_);                                   // launch 9
        k5a<<<grid, 256>>>(w_w, res_w, res_b);
    }
    k5b<<<B_, 256>>>(out);                                  // launch 10
}